// round 6
// baseline (speedup 1.0000x reference)
#include <cuda_runtime.h>
#include <math_constants.h>

#define KVOL 27
#define C4   24                 // 96 channels = 24 float4
#define ROWS_PER_BLOCK 16       // 24*16 = 384 threads

// Flag: 1 if neighbor_map is stored as int64, 0 if int32.
__device__ int g_idx_is64;

__global__ void detect_idx_dtype(const void* __restrict__ nmap,
                                 long long n_in_rows, int elem_count) {
    const long long* p = (const long long*)nmap;
    int avail = elem_count / 2;
    int i = threadIdx.x;
    int bad = 0;
    if (i < avail) {
        long long v = p[i];
        bad = (v < 0 || v >= n_in_rows);
    }
    unsigned any_bad = __ballot_sync(0xFFFFFFFFu, bad);
    __shared__ unsigned s[2];
    if ((threadIdx.x & 31) == 0) s[threadIdx.x >> 5] = any_bad;
    __syncthreads();
    if (threadIdx.x == 0) g_idx_is64 = ((s[0] | s[1]) == 0u) ? 1 : 0;
}

// L2 policy: keep in_feat lines resident within a pass.
__device__ __forceinline__ unsigned long long mk_keep_policy() {
    unsigned long long pol;
    asm("createpolicy.fractional.L2::evict_last.b64 %0, 1.0;" : "=l"(pol));
    return pol;
}

__device__ __forceinline__ float4 ldg_keep(const float4* p, unsigned long long pol) {
    float4 v;
    asm("ld.global.nc.L2::cache_hint.v4.f32 {%0,%1,%2,%3}, [%4], %5;"
        : "=f"(v.x), "=f"(v.y), "=f"(v.z), "=f"(v.w) : "l"(p), "l"(pol));
    return v;
}

__device__ __forceinline__ void vmax(float4& m, const float4 v) {
    m.x = fmaxf(m.x, v.x);
    m.y = fmaxf(m.y, v.y);
    m.z = fmaxf(m.z, v.z);
    m.w = fmaxf(m.w, v.w);
}

// Pool over the neighbors whose index lies in [lo, hi).
// COMBINE: max with the value already in out (previous pass's partial).
template <typename IDX, bool COMBINE>
__device__ __forceinline__ void pool_row_range(const float4* __restrict__ feat,
                                               const IDX* __restrict__ nm,
                                               float4* __restrict__ outp,
                                               int lo, int hi) {
    const unsigned long long pol = mk_keep_policy();
    const float4 NEG = make_float4(-CUDART_INF_F, -CUDART_INF_F,
                                   -CUDART_INF_F, -CUDART_INF_F);
    float4 m = NEG;
    if (COMBINE) m = __ldcs(outp);                     // partial from pass 0
    #pragma unroll
    for (int kb = 0; kb < KVOL; kb += 9) {
        int idx[9];
        bool sel[9];
        #pragma unroll
        for (int j = 0; j < 9; ++j) {
            idx[j] = (int)__ldcs(&nm[kb + j]);         // streaming index read
            sel[j] = (idx[j] >= lo) & (idx[j] < hi);   // warp-uniform predicate
        }
        float4 v[9];
        #pragma unroll
        for (int j = 0; j < 9; ++j)                    // predicated gathers, 9 in flight
            v[j] = sel[j] ? ldg_keep(feat + (long long)idx[j] * C4, pol) : NEG;
        #pragma unroll
        for (int j = 0; j < 9; ++j)
            vmax(m, v[j]);
    }
    __stcs(outp, m);                                   // streaming store
}

template <bool COMBINE>
__global__ __launch_bounds__(C4 * ROWS_PER_BLOCK)
void sparse_maxpool_pass(const float4* __restrict__ in_feat,
                         const void* __restrict__ nmap,
                         float4* __restrict__ out,
                         int n_out, int lo, int hi) {
    int row = blockIdx.x * ROWS_PER_BLOCK + threadIdx.y;
    if (row >= n_out) return;
    int c4 = threadIdx.x;                              // 0..23

    const float4* feat_c = in_feat + c4;
    float4* outp = out + (long long)row * C4 + c4;

    if (g_idx_is64) {
        const long long* nm = (const long long*)nmap + (long long)row * KVOL;
        pool_row_range<long long, COMBINE>(feat_c, nm, outp, lo, hi);
    } else {
        const int* nm = (const int*)nmap + (long long)row * KVOL;
        pool_row_range<int, COMBINE>(feat_c, nm, outp, lo, hi);
    }
}

extern "C" void kernel_launch(void* const* d_in, const int* in_sizes, int n_in,
                              void* d_out, int out_size) {
    const float4* in_feat = (const float4*)d_in[0];
    const void*   nmap    = (const void*)d_in[1];
    float4*       out     = (float4*)d_out;

    int nmap_elems      = in_sizes[1];                    // N_OUT * KVOL
    int n_out           = nmap_elems / KVOL;              // 100000
    int n_in_rows       = in_sizes[0] / 96;               // 400000
    int half            = n_in_rows / 2;

    detect_idx_dtype<<<1, 64>>>(nmap, (long long)n_in_rows, nmap_elems);

    dim3 block(C4, ROWS_PER_BLOCK);
    int grid = (n_out + ROWS_PER_BLOCK - 1) / ROWS_PER_BLOCK;
    // Index-range split: each pass gathers only from half of in_feat
    // (76.8 MB footprint -> fits effective L2), converting the 6.75x
    // random reuse into L2 hits. Pass 1 max-combines with pass 0's result.
    sparse_maxpool_pass<false><<<grid, block>>>(in_feat, nmap, out, n_out, 0, half);
    sparse_maxpool_pass<true ><<<grid, block>>>(in_feat, nmap, out, n_out, half, n_in_rows);
}

// round 7
// speedup vs baseline: 1.3255x; 1.3255x over previous
#include <cuda_runtime.h>
#include <math_constants.h>

#define KVOL 27
#define C4   24                 // 96 channels = 24 float4
#define ROWS_PER_BLOCK 16       // 24*16 = 384 threads

// L2 policy: keep in_feat lines resident (evict-last priority).
__device__ __forceinline__ unsigned long long mk_keep_policy() {
    unsigned long long pol;
    asm("createpolicy.fractional.L2::evict_last.b64 %0, 1.0;" : "=l"(pol));
    return pol;
}

// Gather load: bypass L1 (.cg) — random gathers never hit L1, the lookup only
// adds L1tex queue latency — and apply the evict_last L2 policy.
__device__ __forceinline__ float4 ldg_gather(const float4* p, unsigned long long pol) {
    float4 v;
    asm("ld.global.cg.L2::cache_hint.v4.f32 {%0,%1,%2,%3}, [%4], %5;"
        : "=f"(v.x), "=f"(v.y), "=f"(v.z), "=f"(v.w) : "l"(p), "l"(pol));
    return v;
}

__device__ __forceinline__ void vmax(float4& m, const float4 v) {
    m.x = fmaxf(m.x, v.x);
    m.y = fmaxf(m.y, v.y);
    m.z = fmaxf(m.z, v.z);
    m.w = fmaxf(m.w, v.w);
}

template <typename IDX>
__device__ __forceinline__ void pool_row(const float4* __restrict__ feat,
                                         const IDX* __restrict__ nm,
                                         float4* __restrict__ outp) {
    const unsigned long long pol = mk_keep_policy();
    float4 m = make_float4(-CUDART_INF_F, -CUDART_INF_F, -CUDART_INF_F, -CUDART_INF_F);
    #pragma unroll
    for (int kb = 0; kb < KVOL; kb += 9) {
        int idx[9];                                    // 400000 rows: int is safe
        #pragma unroll
        for (int j = 0; j < 9; ++j)
            idx[j] = (int)__ldcs(&nm[kb + j]);         // streaming index read
        float4 v[9];
        #pragma unroll
        for (int j = 0; j < 9; ++j)
            v[j] = ldg_gather(feat + (long long)idx[j] * C4, pol);  // 9 x 16B in flight
        #pragma unroll
        for (int j = 0; j < 9; ++j)
            vmax(m, v[j]);
    }
    __stcs(outp, m);                                   // streaming store
}

__global__ __launch_bounds__(C4 * ROWS_PER_BLOCK)
void sparse_maxpool_kernel(const float4* __restrict__ in_feat,
                           const void* __restrict__ nmap,
                           float4* __restrict__ out,
                           int n_out, int n_in_rows) {
    // ---- Inline dtype detection (per block; 512B probe, L2-hot) ----
    // Interpreting int32 data as int64 packs two random indices per value and
    // falls outside [0, n_in_rows) within 64 samples w.p. ~1 - 2^-100.
    __shared__ int s_is64;
    int t = threadIdx.y * C4 + threadIdx.x;
    if (t < 64) {
        const long long* p = (const long long*)nmap;
        long long v = p[t];                            // 64*27/2 >> 64 elems: safe
        int bad = (v < 0 || v >= (long long)n_in_rows);
        unsigned any_bad = __ballot_sync(0xFFFFFFFFu, bad);
        if (t == 0) s_is64 = 0;
        __syncwarp();
        if ((t & 31) == 0 && any_bad) atomicOr(&s_is64, 1);
    }
    __syncthreads();
    int is64 = (s_is64 == 0);                          // no bad probes -> int64

    int row = blockIdx.x * ROWS_PER_BLOCK + threadIdx.y;
    if (row >= n_out) return;
    int c4 = threadIdx.x;                              // 0..23

    const float4* feat_c = in_feat + c4;
    float4* outp = out + (long long)row * C4 + c4;

    if (is64) {
        const long long* nm = (const long long*)nmap + (long long)row * KVOL;
        pool_row(feat_c, nm, outp);
    } else {
        const int* nm = (const int*)nmap + (long long)row * KVOL;
        pool_row(feat_c, nm, outp);
    }
}

extern "C" void kernel_launch(void* const* d_in, const int* in_sizes, int n_in,
                              void* d_out, int out_size) {
    const float4* in_feat = (const float4*)d_in[0];
    const void*   nmap    = (const void*)d_in[1];
    float4*       out     = (float4*)d_out;

    int nmap_elems = in_sizes[1];                      // N_OUT * KVOL
    int n_out      = nmap_elems / KVOL;                // 100000
    int n_in_rows  = in_sizes[0] / 96;                 // 400000

    dim3 block(C4, ROWS_PER_BLOCK);
    int grid = (n_out + ROWS_PER_BLOCK - 1) / ROWS_PER_BLOCK;
    sparse_maxpool_kernel<<<grid, block>>>(in_feat, nmap, out, n_out, n_in_rows);
}

// round 8
// speedup vs baseline: 1.3812x; 1.0420x over previous
#include <cuda_runtime.h>
#include <math_constants.h>

#define KVOL 27
#define C4   24                 // 96 channels = 24 float4
#define ROWS_PER_BLOCK 16       // 24*16 = 384 threads

// L2 policy: keep in_feat lines resident (evict-last priority).
__device__ __forceinline__ unsigned long long mk_keep_policy() {
    unsigned long long pol;
    asm("createpolicy.fractional.L2::evict_last.b64 %0, 1.0;" : "=l"(pol));
    return pol;
}

// Gather load: bypass L1 (.cg) + evict_last L2 policy.
__device__ __forceinline__ float4 ldg_gather(const float4* p, unsigned long long pol) {
    float4 v;
    asm("ld.global.cg.L2::cache_hint.v4.f32 {%0,%1,%2,%3}, [%4], %5;"
        : "=f"(v.x), "=f"(v.y), "=f"(v.z), "=f"(v.w) : "l"(p), "l"(pol));
    return v;
}

__device__ __forceinline__ void vmax(float4& m, const float4 v) {
    m.x = fmaxf(m.x, v.x);
    m.y = fmaxf(m.y, v.y);
    m.z = fmaxf(m.z, v.z);
    m.w = fmaxf(m.w, v.w);
}

// Gather B neighbors with all B loads in flight, then reduce.
template <int B, typename IDX>
__device__ __forceinline__ void gather_batch(const float4* __restrict__ feat,
                                             const IDX* __restrict__ nm, int kb,
                                             float4& m, unsigned long long pol) {
    int idx[B];
    #pragma unroll
    for (int j = 0; j < B; ++j)
        idx[j] = (int)__ldcs(&nm[kb + j]);             // streaming index read
    float4 v[B];
    #pragma unroll
    for (int j = 0; j < B; ++j)                        // B x 16B outstanding
        v[j] = ldg_gather(feat + (long long)idx[j] * C4, pol);
    #pragma unroll
    for (int j = 0; j < B; ++j)
        vmax(m, v[j]);
}

template <typename IDX>
__device__ __forceinline__ void pool_row(const float4* __restrict__ feat,
                                         const IDX* __restrict__ nm,
                                         float4* __restrict__ outp) {
    const unsigned long long pol = mk_keep_policy();
    float4 m = make_float4(-CUDART_INF_F, -CUDART_INF_F, -CUDART_INF_F, -CUDART_INF_F);
    gather_batch<14>(feat, nm, 0,  m, pol);            // deep MLP: 14 in flight
    gather_batch<13>(feat, nm, 14, m, pol);            // then 13 in flight
    __stcs(outp, m);                                   // streaming store
}

// minBlocksPerMultiprocessor=2 -> reg cap 85: lets ~14 float4 gathers stay
// live per thread. Occupancy drops (~24 warps/SM) but R5 vs R7 proved TLP is
// in excess; converting it to per-thread MLP raises total outstanding loads.
__global__ __launch_bounds__(C4 * ROWS_PER_BLOCK, 2)
void sparse_maxpool_kernel(const float4* __restrict__ in_feat,
                           const void* __restrict__ nmap,
                           float4* __restrict__ out,
                           int n_out, int n_in_rows) {
    // ---- Inline dtype detection (per block; 512B probe, L2-hot) ----
    __shared__ int s_is64;
    int t = threadIdx.y * C4 + threadIdx.x;
    if (t < 64) {
        const long long* p = (const long long*)nmap;
        long long v = p[t];
        int bad = (v < 0 || v >= (long long)n_in_rows);
        unsigned any_bad = __ballot_sync(0xFFFFFFFFu, bad);
        if (t == 0) s_is64 = 0;
        __syncwarp();
        if ((t & 31) == 0 && any_bad) atomicOr(&s_is64, 1);
    }
    __syncthreads();
    int is64 = (s_is64 == 0);

    int row = blockIdx.x * ROWS_PER_BLOCK + threadIdx.y;
    if (row >= n_out) return;
    int c4 = threadIdx.x;                              // 0..23

    const float4* feat_c = in_feat + c4;
    float4* outp = out + (long long)row * C4 + c4;

    if (is64) {
        const long long* nm = (const long long*)nmap + (long long)row * KVOL;
        pool_row(feat_c, nm, outp);
    } else {
        const int* nm = (const int*)nmap + (long long)row * KVOL;
        pool_row(feat_c, nm, outp);
    }
}

extern "C" void kernel_launch(void* const* d_in, const int* in_sizes, int n_in,
                              void* d_out, int out_size) {
    const float4* in_feat = (const float4*)d_in[0];
    const void*   nmap    = (const void*)d_in[1];
    float4*       out     = (float4*)d_out;

    int nmap_elems = in_sizes[1];                      // N_OUT * KVOL
    int n_out      = nmap_elems / KVOL;                // 100000
    int n_in_rows  = in_sizes[0] / 96;                 // 400000

    dim3 block(C4, ROWS_PER_BLOCK);
    int grid = (n_out + ROWS_PER_BLOCK - 1) / ROWS_PER_BLOCK;
    sparse_maxpool_kernel<<<grid, block>>>(in_feat, nmap, out, n_out, n_in_rows);
}